// round 5
// baseline (speedup 1.0000x reference)
#include <cuda_runtime.h>

// RNN: B=512, T=512, D=64, H=512, O=1
//   h_t = relu(x_t @ W_x + b + h_{t-1} @ W_h),  out = relu(h_T @ W_d + b_d)
//
// R3: 128 CTAs x 512 threads (4 warps/SMSP). Each CTA owns 4 batch rows;
// each thread owns 1 column x 4 rows (4 fp32 accumulators). Scalar LDG of
// W_h column slice (coalesced 128B/warp), broadcast LDS.128 of h.
// unroll 16 for deep MLP. W_x + KC rows of W_h cached in SMEM.

#define BSZ 512
#define TSZ 512
#define DSZ 64
#define HSZ 512
#define ROWS 4
#define NTHR 512
#define NCTA (BSZ / ROWS)   // 128
#define KC   42             // W_h rows cached in SMEM

// smem (floats): wx 32768 | whc KC*512 | hs4 2048 | xs4 256 | wd 512 | br 512
// (final-reduction scratch aliases wx region after the time loop)
#define SMEM_FLOATS (32768 + KC*512 + 2048 + 256 + 512 + 512)
#define SMEM_BYTES  (SMEM_FLOATS * 4)   // 230,400 B <= 232,448 B

__device__ __forceinline__ float4 fma4s(float a, float4 v, float4 acc) {
    acc.x = fmaf(a, v.x, acc.x);
    acc.y = fmaf(a, v.y, acc.y);
    acc.z = fmaf(a, v.z, acc.z);
    acc.w = fmaf(a, v.w, acc.w);
    return acc;
}

__global__ __launch_bounds__(NTHR, 1)
void rnn_persistent_kernel(const float* __restrict__ x,
                           const float* __restrict__ Wx,
                           const float* __restrict__ Wh,
                           const float* __restrict__ brnn,
                           const float* __restrict__ Wd,
                           const float* __restrict__ bd,
                           float* __restrict__ out)
{
    extern __shared__ float smem[];
    float*  wx_s = smem;                                        // [64][512]
    float*  whc  = wx_s + DSZ * HSZ;                            // [KC][512]
    float4* hs4  = reinterpret_cast<float4*>(whc + KC * HSZ);   // [512]
    float4* xs4  = hs4 + HSZ;                                   // [64]
    float*  wd_s = reinterpret_cast<float*>(xs4 + DSZ);         // [512]
    float*  br_s = wd_s + HSZ;                                  // [512]

    const int tid = threadIdx.x;
    const int b0  = blockIdx.x * ROWS;

    // ---- preload W_x, W_h[0:KC], W_d, b_rnn into SMEM ----
    {
        const float4* wxg = reinterpret_cast<const float4*>(Wx);
        float4* d = reinterpret_cast<float4*>(wx_s);
        #pragma unroll 4
        for (int i = tid; i < DSZ * HSZ / 4; i += NTHR) d[i] = wxg[i];
        const float4* whg = reinterpret_cast<const float4*>(Wh);
        float4* wc = reinterpret_cast<float4*>(whc);
        #pragma unroll 4
        for (int i = tid; i < KC * HSZ / 4; i += NTHR) wc[i] = whg[i];
        if (tid < HSZ) {
            wd_s[tid] = Wd[tid];
            br_s[tid] = brnn[tid];
        }
    }
    __syncthreads();

    // thread -> column tid
    const float* wxp = wx_s + tid;   // wx_s[k*512 + tid]
    const float* wcp = whc  + tid;   // whc [k*512 + tid]
    const float* whp = Wh   + tid;   // Wh  [k*512 + tid]

    float4 acc;   // rows 0..3 for this thread's column

    for (int t = 0; t < TSZ; t++) {
        // ---- stage x_t transposed into xs4[k] (256 elems) ----
        if (tid < ROWS * DSZ) {
            int r = tid >> 6;       // 0..3
            int k = tid & 63;       // 0..63
            reinterpret_cast<float*>(xs4)[k * 4 + r] =
                x[((size_t)(b0 + r) * TSZ + t) * DSZ + k];
        }
        __syncthreads();

        // ---- init with bias ----
        {
            float b = br_s[tid];
            acc = make_float4(b, b, b, b);
        }

        // ---- input projection (K=64, SMEM) ----
        #pragma unroll 8
        for (int k = 0; k < DSZ; k++) {
            float  w  = wxp[k * HSZ];
            float4 xv = xs4[k];
            acc = fma4s(w, xv, acc);
        }

        // ---- recurrence (K=512) ----
        if (t > 0) {
            #pragma unroll 7
            for (int k = 0; k < KC; k++) {             // SMEM-cached rows
                float  w  = wcp[k * HSZ];
                float4 hv = hs4[k];
                acc = fma4s(w, hv, acc);
            }
            #pragma unroll 16
            for (int k = KC; k < HSZ; k++) {           // L2-streamed rows
                float  w  = whp[k * HSZ];
                float4 hv = hs4[k];
                acc = fma4s(w, hv, acc);
            }
        }

        __syncthreads();   // all hs4/xs4 reads complete before overwrite

        acc.x = fmaxf(acc.x, 0.f);
        acc.y = fmaxf(acc.y, 0.f);
        acc.z = fmaxf(acc.z, 0.f);
        acc.w = fmaxf(acc.w, 0.f);
        hs4[tid] = acc;
        __syncthreads();   // h_t visible to all warps
    }

    // ---- final dense: out[b] = relu(h_T[b,:] @ W_d + b_d) ----
    // acc holds relu'd final h for column tid, rows 0..3.
    {
        float w = wd_s[tid];
        float4 p;
        p.x = w * acc.x; p.y = w * acc.y; p.z = w * acc.z; p.w = w * acc.w;

        // warp-level reduce (sum across 32 columns)
        #pragma unroll
        for (int off = 16; off > 0; off >>= 1) {
            p.x += __shfl_xor_sync(0xffffffffu, p.x, off);
            p.y += __shfl_xor_sync(0xffffffffu, p.y, off);
            p.z += __shfl_xor_sync(0xffffffffu, p.z, off);
            p.w += __shfl_xor_sync(0xffffffffu, p.w, off);
        }

        float4* wpart = reinterpret_cast<float4*>(wx_s);   // reuse wx region
        if ((tid & 31) == 0)
            wpart[tid >> 5] = p;                            // 16 warp partials
        __syncthreads();

        if (tid < ROWS) {
            float s = 0.f;
            const float* pf = reinterpret_cast<const float*>(wpart);
            #pragma unroll
            for (int i = 0; i < NTHR / 32; i++)
                s += pf[i * 4 + tid];
            out[b0 + tid] = fmaxf(s + bd[0], 0.f);
        }
    }
}

extern "C" void kernel_launch(void* const* d_in, const int* in_sizes, int n_in,
                              void* d_out, int out_size) {
    const float* x    = (const float*)d_in[0];
    const float* Wx   = (const float*)d_in[1];
    const float* Wh   = (const float*)d_in[2];
    const float* brnn = (const float*)d_in[3];
    const float* Wd   = (const float*)d_in[4];
    const float* bd   = (const float*)d_in[5];
    float* out = (float*)d_out;

    cudaFuncSetAttribute(rnn_persistent_kernel,
                         cudaFuncAttributeMaxDynamicSharedMemorySize, SMEM_BYTES);

    rnn_persistent_kernel<<<NCTA, NTHR, SMEM_BYTES>>>(x, Wx, Wh, brnn, Wd, bd, out);
}

// round 8
// speedup vs baseline: 1.8230x; 1.8230x over previous
#include <cuda_runtime.h>

// RNN: B=512, T=512, D=64, H=512, O=1
//   h_t = relu(x_t @ W_x + b + h_{t-1} @ W_h),  out = relu(h_T @ W_d + b_d)
//
// R5: two kernels.
//  1) xw_kernel: XW[t][b][h] = x[b][t] @ W_x + b_rnn  into __device__ scratch.
//  2) rnn kernel: 128 CTAs x 256 thr (R2 shape: 2 cols x 4 rows / thread),
//     FFMA2 (fma.rn.f32x2) packed row-pairs, explicit U=8 LDG prefetch of the
//     W_h stream, KC=104 W_h rows cached in SMEM (x/W_x no longer in SMEM).

#define BSZ 512
#define TSZ 512
#define DSZ 64
#define HSZ 512
#define ROWS 4
#define NTHR 256
#define NCTA (BSZ / ROWS)   // 128
#define KC   104            // W_h rows cached in SMEM (104*512*4 = 208KB? no: 104*2KB = 208K floats*4.. see below)
#define UPF  8              // prefetch depth ( (512-KC) % UPF == 0 )

// main kernel smem (floats): whc KC*512 = 53248 | hs4 2048 | wd 512  -> 55808 f = 223232 B
#define SMEM_MAIN_BYTES ((KC * HSZ + 2048 + 512) * 4)

// xw kernel smem: Wx 64*512 = 32768 f | xs 16*64*4 = 4096 f -> 147456 B
#define TT 16
#define SMEM_XW_BYTES ((DSZ * HSZ + TT * DSZ * ROWS) * 4)

__device__ float g_xw[(size_t)TSZ * BSZ * HSZ];   // [T][B][H] scratch

typedef unsigned long long u64;

__device__ __forceinline__ void ffma2(u64& acc, u64 a, u64 b) {
    asm("fma.rn.f32x2 %0, %1, %2, %0;" : "+l"(acc) : "l"(a), "l"(b));
}
__device__ __forceinline__ u64 pack2(float lo, float hi) {
    u64 r; asm("mov.b64 %0, {%1, %2};" : "=l"(r) : "f"(lo), "f"(hi)); return r;
}
__device__ __forceinline__ void unpack2(float& lo, float& hi, u64 v) {
    asm("mov.b64 {%0, %1}, %2;" : "=f"(lo), "=f"(hi) : "l"(v));
}
__device__ __forceinline__ void add2(u64& acc, u64 a) {
    asm("add.rn.f32x2 %0, %0, %1;" : "+l"(acc) : "l"(a));
}

// ---------------------------------------------------------------------------
// Kernel 1: XW = x @ W_x + b_rnn      (x:[B][T][D], Wx:[D][H] -> XW:[T][B][H])
// grid (T/TT, B/ROWS), 256 threads. Wx cached in SMEM; FFMA2 row-pair packed.
// ---------------------------------------------------------------------------
__global__ __launch_bounds__(NTHR, 1)
void xw_kernel(const float* __restrict__ x,
               const float* __restrict__ Wx,
               const float* __restrict__ brnn)
{
    extern __shared__ float smem[];
    float* wx_s = smem;                  // [64][512]
    float* xs   = wx_s + DSZ * HSZ;      // [TT][64][4]  (d-major, 4 b-rows packed)

    const int tid = threadIdx.x;
    const int t0  = blockIdx.x * TT;
    const int b0  = blockIdx.y * ROWS;

    // load Wx into SMEM
    {
        const float4* g = reinterpret_cast<const float4*>(Wx);
        float4* d = reinterpret_cast<float4*>(wx_s);
        #pragma unroll 8
        for (int i = tid; i < DSZ * HSZ / 4; i += NTHR) d[i] = g[i];
    }
    // load x tile transposed: xs[t][d*4 + r] = x[b0+r][t0+t][d]
    #pragma unroll
    for (int i = 0; i < TT * DSZ * ROWS / NTHR; i++) {
        int idx = tid + i * NTHR;
        int d = idx & 63;
        int t = (idx >> 6) & (TT - 1);
        int r = idx >> 10;
        xs[(t * DSZ + d) * 4 + r] = x[((size_t)(b0 + r) * TSZ + t0 + t) * DSZ + d];
    }
    __syncthreads();

    const float2* wx2 = reinterpret_cast<const float2*>(wx_s) + tid;  // cols 2tid,2tid+1
    float bA = brnn[2 * tid], bB = brnn[2 * tid + 1];
    u64 bA2 = pack2(bA, bA), bB2 = pack2(bB, bB);

    float2* xwo = reinterpret_cast<float2*>(g_xw);

    for (int t = 0; t < TT; t++) {
        u64 a01 = bA2, a23 = bA2, c01 = bB2, c23 = bB2;
        const ulonglong2* xv = reinterpret_cast<const ulonglong2*>(xs + t * DSZ * 4);
        #pragma unroll 8
        for (int k = 0; k < DSZ; k++) {
            float2 w = wx2[k * (HSZ / 2)];
            ulonglong2 hv = xv[k];
            u64 wA = pack2(w.x, w.x);
            u64 wB = pack2(w.y, w.y);
            ffma2(a01, wA, hv.x);
            ffma2(a23, wA, hv.y);
            ffma2(c01, wB, hv.x);
            ffma2(c23, wB, hv.y);
        }
        // write XW[t0+t][b0+r][2tid .. 2tid+1]
        float a0, a1, a2, a3, c0, c1, c2, c3;
        unpack2(a0, a1, a01); unpack2(a2, a3, a23);
        unpack2(c0, c1, c01); unpack2(c2, c3, c23);
        size_t base = ((size_t)(t0 + t) * BSZ + b0) * (HSZ / 2) + tid;
        xwo[base]                  = make_float2(a0, c0);
        xwo[base + (HSZ / 2)]      = make_float2(a1, c1);
        xwo[base + 2 * (HSZ / 2)]  = make_float2(a2, c2);
        xwo[base + 3 * (HSZ / 2)]  = make_float2(a3, c3);
    }
}

// ---------------------------------------------------------------------------
// Kernel 2: persistent recurrence. 128 CTAs x 256 threads, 4 rows/CTA.
// ---------------------------------------------------------------------------
__global__ __launch_bounds__(NTHR, 1)
void rnn_persistent_kernel(const float* __restrict__ Wh,
                           const float* __restrict__ Wd,
                           const float* __restrict__ bd,
                           float* __restrict__ out)
{
    extern __shared__ float smem[];
    float*  whc  = smem;                                        // [KC][512]
    float4* hs4  = reinterpret_cast<float4*>(whc + KC * HSZ);   // [512] (4 rows packed)
    float*  wd_s = reinterpret_cast<float*>(hs4 + HSZ);         // [512]

    const int tid = threadIdx.x;
    const int b0  = blockIdx.x * ROWS;

    // preload W_h[0:KC] and W_d
    {
        const float4* g = reinterpret_cast<const float4*>(Wh);
        float4* d = reinterpret_cast<float4*>(whc);
        #pragma unroll 8
        for (int i = tid; i < KC * HSZ / 4; i += NTHR) d[i] = g[i];
        wd_s[tid] = Wd[tid];
        wd_s[tid + NTHR] = Wd[tid + NTHR];
    }
    __syncthreads();

    const float2*     wcp = reinterpret_cast<const float2*>(whc) + tid;  // cached rows
    const float2*     whp = reinterpret_cast<const float2*>(Wh) + tid;   // streamed rows
    const ulonglong2* hsu = reinterpret_cast<const ulonglong2*>(hs4);
    const float2*     xw2 = reinterpret_cast<const float2*>(g_xw);

    for (int t = 0; t < TSZ; t++) {
        // issue XW loads early; consumed only after the k-loops
        size_t xb = ((size_t)t * BSZ + b0) * (HSZ / 2) + tid;
        float2 x0 = xw2[xb];
        float2 x1 = xw2[xb + (HSZ / 2)];
        float2 x2 = xw2[xb + 2 * (HSZ / 2)];
        float2 x3 = xw2[xb + 3 * (HSZ / 2)];

        u64 a01 = 0, a23 = 0, c01 = 0, c23 = 0;   // 0x0 == packed {0.f,0.f}

        if (t > 0) {
            // ---- SMEM-cached W_h rows ----
            #pragma unroll 8
            for (int k = 0; k < KC; k++) {
                float2 w = wcp[k * (HSZ / 2)];
                ulonglong2 hv = hsu[k];
                u64 wA = pack2(w.x, w.x);
                u64 wB = pack2(w.y, w.y);
                ffma2(a01, wA, hv.x);
                ffma2(a23, wA, hv.y);
                ffma2(c01, wB, hv.x);
                ffma2(c23, wB, hv.y);
            }
            // ---- L2-streamed W_h rows, explicit U-deep prefetch ----
            float2 wreg[UPF];
            #pragma unroll
            for (int u = 0; u < UPF; u++)
                wreg[u] = whp[(KC + u) * (HSZ / 2)];

            for (int kb = KC; kb < HSZ; kb += UPF) {
                float2 wcur[UPF];
                #pragma unroll
                for (int u = 0; u < UPF; u++) wcur[u] = wreg[u];
                if (kb + UPF < HSZ) {
                    #pragma unroll
                    for (int u = 0; u < UPF; u++)
                        wreg[u] = whp[(kb + UPF + u) * (HSZ / 2)];
                }
                #pragma unroll
                for (int u = 0; u < UPF; u++) {
                    ulonglong2 hv = hsu[kb + u];
                    u64 wA = pack2(wcur[u].x, wcur[u].x);
                    u64 wB = pack2(wcur[u].y, wcur[u].y);
                    ffma2(a01, wA, hv.x);
                    ffma2(a23, wA, hv.y);
                    ffma2(c01, wB, hv.x);
                    ffma2(c23, wB, hv.y);
                }
            }
        }

        // add input projection
        add2(a01, pack2(x0.x, x1.x));
        add2(a23, pack2(x2.x, x3.x));
        add2(c01, pack2(x0.y, x1.y));
        add2(c23, pack2(x2.y, x3.y));

        __syncthreads();   // all hsu reads complete before overwrite

        float a0, a1, a2, a3, c0, c1, c2, c3;
        unpack2(a0, a1, a01); unpack2(a2, a3, a23);
        unpack2(c0, c1, c01); unpack2(c2, c3, c23);
        hs4[2 * tid + 0] = make_float4(fmaxf(a0, 0.f), fmaxf(a1, 0.f),
                                       fmaxf(a2, 0.f), fmaxf(a3, 0.f));
        hs4[2 * tid + 1] = make_float4(fmaxf(c0, 0.f), fmaxf(c1, 0.f),
                                       fmaxf(c2, 0.f), fmaxf(c3, 0.f));
        __syncthreads();   // h_t visible to all warps
    }

    // ---- final dense: out[b] = relu(h_T[b,:] @ W_d + b_d) ----
    {
        float wA = wd_s[2 * tid], wB = wd_s[2 * tid + 1];
        float4 hA = hs4[2 * tid], hB = hs4[2 * tid + 1];
        float4 p;
        p.x = wA * hA.x + wB * hB.x;
        p.y = wA * hA.y + wB * hB.y;
        p.z = wA * hA.z + wB * hB.z;
        p.w = wA * hA.w + wB * hB.w;

        #pragma unroll
        for (int off = 16; off > 0; off >>= 1) {
            p.x += __shfl_xor_sync(0xffffffffu, p.x, off);
            p.y += __shfl_xor_sync(0xffffffffu, p.y, off);
            p.z += __shfl_xor_sync(0xffffffffu, p.z, off);
            p.w += __shfl_xor_sync(0xffffffffu, p.w, off);
        }
        __syncthreads();                                   // hs4 reads done
        float4* wpart = reinterpret_cast<float4*>(smem);   // reuse whc region
        if ((tid & 31) == 0)
            wpart[tid >> 5] = p;                           // 8 warp partials
        __syncthreads();

        if (tid < ROWS) {
            float s = 0.f;
            const float* pf = reinterpret_cast<const float*>(wpart);
            #pragma unroll
            for (int i = 0; i < NTHR / 32; i++)
                s += pf[i * 4 + tid];
            out[b0 + tid] = fmaxf(s + bd[0], 0.f);
        }
    }
}

extern "C" void kernel_launch(void* const* d_in, const int* in_sizes, int n_in,
                              void* d_out, int out_size) {
    const float* x    = (const float*)d_in[0];
    const float* Wx   = (const float*)d_in[1];
    const float* Wh   = (const float*)d_in[2];
    const float* brnn = (const float*)d_in[3];
    const float* Wd   = (const float*)d_in[4];
    const float* bd   = (const float*)d_in[5];
    float* out = (float*)d_out;

    cudaFuncSetAttribute(xw_kernel,
                         cudaFuncAttributeMaxDynamicSharedMemorySize, SMEM_XW_BYTES);
    cudaFuncSetAttribute(rnn_persistent_kernel,
                         cudaFuncAttributeMaxDynamicSharedMemorySize, SMEM_MAIN_BYTES);

    dim3 gxw(TSZ / TT, BSZ / ROWS);
    xw_kernel<<<gxw, NTHR, SMEM_XW_BYTES>>>(x, Wx, brnn);
    rnn_persistent_kernel<<<NCTA, NTHR, SMEM_MAIN_BYTES>>>(Wh, Wd, bd, out);
}

// round 9
// speedup vs baseline: 2.4501x; 1.3440x over previous
#include <cuda_runtime.h>
#include <cstdint>

// RNN: B=512, T=512, D=64, H=512, O=1
// R6: cluster k-split.
//  - xw_kernel: XW[t][b][h] = x @ W_x + b_rnn  (unchanged from R5)
//  - rnn_cluster_kernel: 64 clusters x 2 CTAs (128 CTAs, 256 thr).
//    Cluster owns 8 batch rows; CTA rank r owns k-half/j-half [r*256,(r+1)*256).
//    Per step: partials over own k-half for all 512 j; foreign-j half (8KB)
//    exchanged via DSMEM (double-buffered by t parity, one cluster.sync/step).
//    KC=96 rows of own W_h half cached in SMEM; rest streamed with UPF=8
//    register prefetch. FFMA2 packed row-pairs throughout.

#define BSZ 512
#define TSZ 512
#define DSZ 64
#define HSZ 512
#define KH  256       // k-rows per CTA (half)
#define CROWS 8       // batch rows per cluster
#define NTHR 256
#define NCTA 128
#define KC   96       // cached W_h rows (of own half)
#define UPF  8        // prefetch depth; (KH-KC) % UPF == 0
#define KSTRIDE 12    // h smem k-stride in floats (48B, 16B-aligned, less STS conflict)

// rnn smem floats: whc KC*512=49152 | h KH*12=3072 | xbuf 2*128*16=4096 | wd 512
#define SMEM_MAIN_BYTES ((KC*HSZ + KH*KSTRIDE + 2*128*16 + 512) * 4)   // 227328

#define TT 16
#define SMEM_XW_BYTES ((DSZ * HSZ + TT * DSZ * 4) * 4)

__device__ float g_xw[(size_t)TSZ * BSZ * HSZ];   // [T][B][H] scratch

typedef unsigned long long u64;

__device__ __forceinline__ void ffma2(u64& acc, u64 a, u64 b) {
    asm("fma.rn.f32x2 %0, %1, %2, %0;" : "+l"(acc) : "l"(a), "l"(b));
}
__device__ __forceinline__ u64 pack2(float lo, float hi) {
    u64 r; asm("mov.b64 %0, {%1, %2};" : "=l"(r) : "f"(lo), "f"(hi)); return r;
}
__device__ __forceinline__ void unpack2(float& lo, float& hi, u64 v) {
    asm("mov.b64 {%0, %1}, %2;" : "=f"(lo), "=f"(hi) : "l"(v));
}
__device__ __forceinline__ uint32_t smem_u32(const void* p) {
    uint32_t a;
    asm("{ .reg .u64 t; cvta.to.shared.u64 t, %1; cvt.u32.u64 %0, t; }"
        : "=r"(a) : "l"(p));
    return a;
}
__device__ __forceinline__ uint32_t mapa_peer(uint32_t addr, uint32_t peer) {
    uint32_t r;
    asm("mapa.shared::cluster.u32 %0, %1, %2;" : "=r"(r) : "r"(addr), "r"(peer));
    return r;
}
__device__ __forceinline__ float4 ld_cluster_f4(uint32_t a) {
    float4 v;
    asm volatile("ld.shared::cluster.v4.f32 {%0,%1,%2,%3}, [%4];"
                 : "=f"(v.x), "=f"(v.y), "=f"(v.z), "=f"(v.w) : "r"(a));
    return v;
}
__device__ __forceinline__ float ld_cluster_f32(uint32_t a) {
    float v;
    asm volatile("ld.shared::cluster.f32 %0, [%1];" : "=f"(v) : "r"(a));
    return v;
}
#define CLUSTER_SYNC() do { \
    asm volatile("barrier.cluster.arrive.aligned;" ::: "memory"); \
    asm volatile("barrier.cluster.wait.aligned;"   ::: "memory"); \
} while (0)

// ---------------------------------------------------------------------------
// Kernel 1: XW = x @ W_x + b_rnn   (x:[B][T][D], Wx:[D][H] -> XW:[T][B][H])
// ---------------------------------------------------------------------------
__global__ __launch_bounds__(NTHR, 1)
void xw_kernel(const float* __restrict__ x,
               const float* __restrict__ Wx,
               const float* __restrict__ brnn)
{
    extern __shared__ float smem[];
    float* wx_s = smem;                  // [64][512]
    float* xs   = wx_s + DSZ * HSZ;      // [TT][64][4]

    const int tid = threadIdx.x;
    const int t0  = blockIdx.x * TT;
    const int b0  = blockIdx.y * 4;

    {
        const float4* g = reinterpret_cast<const float4*>(Wx);
        float4* d = reinterpret_cast<float4*>(wx_s);
        #pragma unroll 8
        for (int i = tid; i < DSZ * HSZ / 4; i += NTHR) d[i] = g[i];
    }
    #pragma unroll
    for (int i = 0; i < TT * DSZ * 4 / NTHR; i++) {
        int idx = tid + i * NTHR;
        int d = idx & 63;
        int t = (idx >> 6) & (TT - 1);
        int r = idx >> 10;
        xs[(t * DSZ + d) * 4 + r] = x[((size_t)(b0 + r) * TSZ + t0 + t) * DSZ + d];
    }
    __syncthreads();

    const float2* wx2 = reinterpret_cast<const float2*>(wx_s) + tid;
    float bA = brnn[2 * tid], bB = brnn[2 * tid + 1];
    u64 bA2 = pack2(bA, bA), bB2 = pack2(bB, bB);

    float2* xwo = reinterpret_cast<float2*>(g_xw);

    for (int t = 0; t < TT; t++) {
        u64 a01 = bA2, a23 = bA2, c01 = bB2, c23 = bB2;
        const ulonglong2* xv = reinterpret_cast<const ulonglong2*>(xs + t * DSZ * 4);
        #pragma unroll 8
        for (int k = 0; k < DSZ; k++) {
            float2 w = wx2[k * (HSZ / 2)];
            ulonglong2 hv = xv[k];
            u64 wA = pack2(w.x, w.x);
            u64 wB = pack2(w.y, w.y);
            ffma2(a01, wA, hv.x);
            ffma2(a23, wA, hv.y);
            ffma2(c01, wB, hv.x);
            ffma2(c23, wB, hv.y);
        }
        float a0, a1, a2, a3, c0, c1, c2, c3;
        unpack2(a0, a1, a01); unpack2(a2, a3, a23);
        unpack2(c0, c1, c01); unpack2(c2, c3, c23);
        size_t base = ((size_t)(t0 + t) * BSZ + b0) * (HSZ / 2) + tid;
        xwo[base]                 = make_float2(a0, c0);
        xwo[base + (HSZ / 2)]     = make_float2(a1, c1);
        xwo[base + 2 * (HSZ / 2)] = make_float2(a2, c2);
        xwo[base + 3 * (HSZ / 2)] = make_float2(a3, c3);
    }
}

// ---------------------------------------------------------------------------
// Kernel 2: clustered persistent recurrence.
// ---------------------------------------------------------------------------
__global__ __launch_bounds__(NTHR, 1) __cluster_dims__(2, 1, 1)
void rnn_cluster_kernel(const float* __restrict__ Wh,
                        const float* __restrict__ Wd,
                        const float* __restrict__ bd,
                        float* __restrict__ out)
{
    extern __shared__ float smem[];
    float* whc  = smem;                         // [KC][512]  own-half cached W_h rows
    float* hsm  = whc + KC * HSZ;               // [KH][KSTRIDE]  own j-half of h (8 rows)
    float* xbf  = hsm + KH * KSTRIDE;           // [2][128][16]  exchange buffers
    float* wd_s = xbf + 2 * 128 * 16;           // [512]

    const int tid = threadIdx.x;
    uint32_t rank;
    asm("mov.u32 %0, %%cluster_ctarank;" : "=r"(rank));
    const uint32_t peer = rank ^ 1u;
    const int b0 = (blockIdx.x >> 1) * CROWS;
    const bool own = ((uint32_t)(tid >> 7) == rank);   // this thread's cols in own j-half?
    const int lp = tid & 127;                          // local pair index

    // ---- preload own W_h half rows [0,KC) and W_d ----
    {
        const float4* g = reinterpret_cast<const float4*>(Wh + (size_t)rank * KH * HSZ);
        float4* d = reinterpret_cast<float4*>(whc);
        #pragma unroll 8
        for (int i = tid; i < KC * HSZ / 4; i += NTHR) d[i] = g[i];
        wd_s[tid] = Wd[tid];
        wd_s[tid + 256] = Wd[tid + 256];
    }
    __syncthreads();

    const float2* wc2 = reinterpret_cast<const float2*>(whc) + tid;
    const float2* wg2 = reinterpret_cast<const float2*>(Wh)
                        + ((size_t)rank * KH + KC) * (HSZ / 2) + tid;
    const float2* xw2 = reinterpret_cast<const float2*>(g_xw);
    const uint32_t xb_base = smem_u32(xbf);

    for (int t = 0; t < TSZ; t++) {
        const int p = t & 1;

        // early global loads of xw for our 8 rows (consumed in finalize)
        float2 xr[CROWS];
        if (own) {
            #pragma unroll
            for (int r = 0; r < CROWS; r++)
                xr[r] = xw2[((size_t)t * BSZ + b0 + r) * (HSZ / 2) + tid];
        }

        u64 A01 = 0, A23 = 0, A45 = 0, A67 = 0;
        u64 C01 = 0, C23 = 0, C45 = 0, C67 = 0;

        if (t > 0) {
            // ---- cached rows ----
            #pragma unroll 8
            for (int k = 0; k < KC; k++) {
                float2 w = wc2[k * (HSZ / 2)];
                ulonglong2 hA = *reinterpret_cast<const ulonglong2*>(hsm + k * KSTRIDE);
                ulonglong2 hB = *reinterpret_cast<const ulonglong2*>(hsm + k * KSTRIDE + 4);
                u64 wA = pack2(w.x, w.x), wB = pack2(w.y, w.y);
                ffma2(A01, wA, hA.x); ffma2(A23, wA, hA.y);
                ffma2(A45, wA, hB.x); ffma2(A67, wA, hB.y);
                ffma2(C01, wB, hA.x); ffma2(C23, wB, hA.y);
                ffma2(C45, wB, hB.x); ffma2(C67, wB, hB.y);
            }
            // ---- streamed rows with register prefetch ----
            float2 wreg[UPF];
            #pragma unroll
            for (int u = 0; u < UPF; u++)
                wreg[u] = wg2[u * (HSZ / 2)];

            for (int kb = KC; kb < KH; kb += UPF) {
                float2 wcur[UPF];
                #pragma unroll
                for (int u = 0; u < UPF; u++) wcur[u] = wreg[u];
                if (kb + UPF < KH) {
                    #pragma unroll
                    for (int u = 0; u < UPF; u++)
                        wreg[u] = wg2[(size_t)(kb - KC + UPF + u) * (HSZ / 2)];
                }
                #pragma unroll
                for (int u = 0; u < UPF; u++) {
                    int k = kb + u;
                    ulonglong2 hA = *reinterpret_cast<const ulonglong2*>(hsm + k * KSTRIDE);
                    ulonglong2 hB = *reinterpret_cast<const ulonglong2*>(hsm + k * KSTRIDE + 4);
                    u64 wA = pack2(wcur[u].x, wcur[u].x), wB = pack2(wcur[u].y, wcur[u].y);
                    ffma2(A01, wA, hA.x); ffma2(A23, wA, hA.y);
                    ffma2(A45, wA, hB.x); ffma2(A67, wA, hB.y);
                    ffma2(C01, wB, hA.x); ffma2(C23, wB, hA.y);
                    ffma2(C45, wB, hB.x); ffma2(C67, wB, hB.y);
                }
            }
        }

        float a0, a1, a2, a3, a4, a5, a6, a7;
        float c0, c1, c2, c3, c4, c5, c6, c7;
        unpack2(a0, a1, A01); unpack2(a2, a3, A23);
        unpack2(a4, a5, A45); unpack2(a6, a7, A67);
        unpack2(c0, c1, C01); unpack2(c2, c3, C23);
        unpack2(c4, c5, C45); unpack2(c6, c7, C67);

        if (!own) {
            // ship foreign-j partial into our own exchange buffer
            float4* dst = reinterpret_cast<float4*>(xbf) + (p * 128 + lp) * 4;
            dst[0] = make_float4(a0, a1, a2, a3);
            dst[1] = make_float4(a4, a5, a6, a7);
            dst[2] = make_float4(c0, c1, c2, c3);
            dst[3] = make_float4(c4, c5, c6, c7);
        }

        CLUSTER_SYNC();   // peer's foreign partials now visible; hsm reads drained

        if (own) {
            uint32_t pa = mapa_peer(xb_base + (uint32_t)(p * 128 + lp) * 64, peer);
            float4 q0 = ld_cluster_f4(pa);
            float4 q1 = ld_cluster_f4(pa + 16);
            float4 q2 = ld_cluster_f4(pa + 32);
            float4 q3 = ld_cluster_f4(pa + 48);

            const int jlA = 2 * lp, jlB = jlA + 1;
            float* hA = hsm + jlA * KSTRIDE;
            float* hB = hsm + jlB * KSTRIDE;
            *reinterpret_cast<float4*>(hA) = make_float4(
                fmaxf(a0 + q0.x + xr[0].x, 0.f), fmaxf(a1 + q0.y + xr[1].x, 0.f),
                fmaxf(a2 + q0.z + xr[2].x, 0.f), fmaxf(a3 + q0.w + xr[3].x, 0.f));
            *reinterpret_cast<float4*>(hA + 4) = make_float4(
                fmaxf(a4 + q1.x + xr[4].x, 0.f), fmaxf(a5 + q1.y + xr[5].x, 0.f),
                fmaxf(a6 + q1.z + xr[6].x, 0.f), fmaxf(a7 + q1.w + xr[7].x, 0.f));
            *reinterpret_cast<float4*>(hB) = make_float4(
                fmaxf(c0 + q2.x + xr[0].y, 0.f), fmaxf(c1 + q2.y + xr[1].y, 0.f),
                fmaxf(c2 + q2.z + xr[2].y, 0.f), fmaxf(c3 + q2.w + xr[3].y, 0.f));
            *reinterpret_cast<float4*>(hB + 4) = make_float4(
                fmaxf(c4 + q3.x + xr[4].y, 0.f), fmaxf(c5 + q3.y + xr[5].y, 0.f),
                fmaxf(c6 + q3.z + xr[6].y, 0.f), fmaxf(c7 + q3.w + xr[7].y, 0.f));
        }
        __syncthreads();   // h_t visible CTA-wide for next step
    }

    // ---- final dense: out[b] = relu(h_T[b,:] @ W_d + b_d) ----
    {
        const int wr = tid >> 5;      // warp 0..7 -> row
        const int l  = tid & 31;
        float s = 0.f;
        #pragma unroll
        for (int i = 0; i < 8; i++) {
            int jl = l * 8 + i;
            s += hsm[jl * KSTRIDE + wr] * wd_s[rank * KH + jl];
        }
        #pragma unroll
        for (int off = 16; off > 0; off >>= 1)
            s += __shfl_xor_sync(0xffffffffu, s, off);

        if (rank == 1 && l == 0) xbf[wr] = s;
        CLUSTER_SYNC();
        if (rank == 0 && l == 0) {
            float sp = ld_cluster_f32(mapa_peer(xb_base + (uint32_t)wr * 4, peer));
            out[b0 + wr] = fmaxf(s + sp + bd[0], 0.f);
        }
        CLUSTER_SYNC();   // keep peer smem alive until reads complete
    }
}

extern "C" void kernel_launch(void* const* d_in, const int* in_sizes, int n_in,
                              void* d_out, int out_size) {
    const float* x    = (const float*)d_in[0];
    const float* Wx   = (const float*)d_in[1];
    const float* Wh   = (const float*)d_in[2];
    const float* brnn = (const float*)d_in[3];
    const float* Wd   = (const float*)d_in[4];
    const float* bd   = (const float*)d_in[5];
    float* out = (float*)d_out;

    cudaFuncSetAttribute(xw_kernel,
                         cudaFuncAttributeMaxDynamicSharedMemorySize, SMEM_XW_BYTES);
    cudaFuncSetAttribute(rnn_cluster_kernel,
                         cudaFuncAttributeMaxDynamicSharedMemorySize, SMEM_MAIN_BYTES);

    dim3 gxw(TSZ / TT, BSZ / 4);
    xw_kernel<<<gxw, NTHR, SMEM_XW_BYTES>>>(x, Wx, brnn);
    rnn_cluster_kernel<<<NCTA, NTHR, SMEM_MAIN_BYTES>>>(Wh, Wd, bd, out);
}

// round 10
// speedup vs baseline: 2.4593x; 1.0038x over previous
#include <cuda_runtime.h>
#include <cstdint>

// RNN: B=512, T=512, D=64, H=512, O=1
// R7: cluster k-split (2 CTAs/cluster) + intra-CTA k-split (2 warp-groups).
//  512 thr/CTA (4 warps/SMSP). wg owns 128 k-rows; thread = 2 cols x 8 rows.
//  wg1 partials reduced into wg0 via conflict-free float4 smem scratch.
//  DSMEM exchange of foreign j-half unchanged from R6.

#define BSZ 512
#define TSZ 512
#define DSZ 64
#define HSZ 512
#define KH  256       // k-rows per CTA
#define CROWS 8       // batch rows per cluster
#define NTHR 512
#define NCTA 128
#define KCG  40       // cached W_h rows per k-group (80/CTA)
#define KSTR 88       // streamed rows per group
#define UPF  8        // 88 % 8 == 0
#define KSTRIDE 12    // h smem k-stride in floats

// smem floats: whc 2*40*512=40960 | hsm 256*12=3072 | xbf 2*128*16=4096
//              red 4*256*4=4096 | wd 512   -> 52736 f = 210944 B
#define SMEM_MAIN_BYTES ((2*KCG*HSZ + KH*KSTRIDE + 2*128*16 + 4*256*4 + 512) * 4)

#define TT 16
#define SMEM_XW_BYTES ((DSZ * HSZ + TT * DSZ * 4) * 4)
#define NTHRX 256

__device__ float g_xw[(size_t)TSZ * BSZ * HSZ];   // [T][B][H]

typedef unsigned long long u64;

__device__ __forceinline__ void ffma2(u64& acc, u64 a, u64 b) {
    asm("fma.rn.f32x2 %0, %1, %2, %0;" : "+l"(acc) : "l"(a), "l"(b));
}
__device__ __forceinline__ u64 pack2(float lo, float hi) {
    u64 r; asm("mov.b64 %0, {%1, %2};" : "=l"(r) : "f"(lo), "f"(hi)); return r;
}
__device__ __forceinline__ void unpack2(float& lo, float& hi, u64 v) {
    asm("mov.b64 {%0, %1}, %2;" : "=f"(lo), "=f"(hi) : "l"(v));
}
__device__ __forceinline__ uint32_t smem_u32(const void* p) {
    uint32_t a;
    asm("{ .reg .u64 t; cvta.to.shared.u64 t, %1; cvt.u32.u64 %0, t; }"
        : "=r"(a) : "l"(p));
    return a;
}
__device__ __forceinline__ uint32_t mapa_peer(uint32_t addr, uint32_t peer) {
    uint32_t r;
    asm("mapa.shared::cluster.u32 %0, %1, %2;" : "=r"(r) : "r"(addr), "r"(peer));
    return r;
}
__device__ __forceinline__ float4 ld_cluster_f4(uint32_t a) {
    float4 v;
    asm volatile("ld.shared::cluster.v4.f32 {%0,%1,%2,%3}, [%4];"
                 : "=f"(v.x), "=f"(v.y), "=f"(v.z), "=f"(v.w) : "r"(a));
    return v;
}
__device__ __forceinline__ float ld_cluster_f32(uint32_t a) {
    float v;
    asm volatile("ld.shared::cluster.f32 %0, [%1];" : "=f"(v) : "r"(a));
    return v;
}
#define CLUSTER_SYNC() do { \
    asm volatile("barrier.cluster.arrive.aligned;" ::: "memory"); \
    asm volatile("barrier.cluster.wait.aligned;"   ::: "memory"); \
} while (0)

// ---------------------------------------------------------------------------
// Kernel 1: XW = x @ W_x + b_rnn   (unchanged from R6)
// ---------------------------------------------------------------------------
__global__ __launch_bounds__(NTHRX, 1)
void xw_kernel(const float* __restrict__ x,
               const float* __restrict__ Wx,
               const float* __restrict__ brnn)
{
    extern __shared__ float smem[];
    float* wx_s = smem;
    float* xs   = wx_s + DSZ * HSZ;

    const int tid = threadIdx.x;
    const int t0  = blockIdx.x * TT;
    const int b0  = blockIdx.y * 4;

    {
        const float4* g = reinterpret_cast<const float4*>(Wx);
        float4* d = reinterpret_cast<float4*>(wx_s);
        #pragma unroll 8
        for (int i = tid; i < DSZ * HSZ / 4; i += NTHRX) d[i] = g[i];
    }
    #pragma unroll
    for (int i = 0; i < TT * DSZ * 4 / NTHRX; i++) {
        int idx = tid + i * NTHRX;
        int d = idx & 63;
        int t = (idx >> 6) & (TT - 1);
        int r = idx >> 10;
        xs[(t * DSZ + d) * 4 + r] = x[((size_t)(b0 + r) * TSZ + t0 + t) * DSZ + d];
    }
    __syncthreads();

    const float2* wx2 = reinterpret_cast<const float2*>(wx_s) + tid;
    float bA = brnn[2 * tid], bB = brnn[2 * tid + 1];
    u64 bA2 = pack2(bA, bA), bB2 = pack2(bB, bB);

    float2* xwo = reinterpret_cast<float2*>(g_xw);

    for (int t = 0; t < TT; t++) {
        u64 a01 = bA2, a23 = bA2, c01 = bB2, c23 = bB2;
        const ulonglong2* xv = reinterpret_cast<const ulonglong2*>(xs + t * DSZ * 4);
        #pragma unroll 8
        for (int k = 0; k < DSZ; k++) {
            float2 w = wx2[k * (HSZ / 2)];
            ulonglong2 hv = xv[k];
            u64 wA = pack2(w.x, w.x);
            u64 wB = pack2(w.y, w.y);
            ffma2(a01, wA, hv.x);
            ffma2(a23, wA, hv.y);
            ffma2(c01, wB, hv.x);
            ffma2(c23, wB, hv.y);
        }
        float a0, a1, a2, a3, c0, c1, c2, c3;
        unpack2(a0, a1, a01); unpack2(a2, a3, a23);
        unpack2(c0, c1, c01); unpack2(c2, c3, c23);
        size_t base = ((size_t)(t0 + t) * BSZ + b0) * (HSZ / 2) + tid;
        xwo[base]                 = make_float2(a0, c0);
        xwo[base + (HSZ / 2)]     = make_float2(a1, c1);
        xwo[base + 2 * (HSZ / 2)] = make_float2(a2, c2);
        xwo[base + 3 * (HSZ / 2)] = make_float2(a3, c3);
    }
}

// ---------------------------------------------------------------------------
// Kernel 2: clustered persistent recurrence, 512 threads, dual k-groups.
// ---------------------------------------------------------------------------
__global__ __launch_bounds__(NTHR, 1) __cluster_dims__(2, 1, 1)
void rnn_cluster_kernel(const float* __restrict__ Wh,
                        const float* __restrict__ Wd,
                        const float* __restrict__ bd,
                        float* __restrict__ out)
{
    extern __shared__ float smem[];
    float*  whc  = smem;                              // [2][KCG][512]
    float*  hsm  = whc + 2 * KCG * HSZ;               // [KH][KSTRIDE]
    float*  xbf  = hsm + KH * KSTRIDE;                // [2][128][16]
    float4* red  = reinterpret_cast<float4*>(xbf + 2 * 128 * 16);  // [4][256]
    float*  wd_s = reinterpret_cast<float*>(red + 4 * 256);        // [512]

    const int tid = threadIdx.x;
    uint32_t rank;
    asm("mov.u32 %0, %%cluster_ctarank;" : "=r"(rank));
    const uint32_t peer = rank ^ 1u;
    const int b0  = (blockIdx.x >> 1) * CROWS;
    const int wg  = tid >> 8;            // k-group 0/1
    const int lp2 = tid & 255;           // col-pair index (cols 2lp2, 2lp2+1)
    const bool g0  = (wg == 0);
    const bool own = g0 && ((lp2 >> 7) == (int)rank);
    const int  lp  = lp2 & 127;

    // ---- preload cached W_h rows (both groups) and W_d ----
    {
        const float4* s0 = reinterpret_cast<const float4*>(Wh + ((size_t)rank * KH) * HSZ);
        const float4* s1 = reinterpret_cast<const float4*>(Wh + ((size_t)rank * KH + 128) * HSZ);
        float4* d = reinterpret_cast<float4*>(whc);
        #pragma unroll 4
        for (int i = tid; i < KCG * HSZ / 4; i += NTHR) {
            d[i] = s0[i];
            d[i + KCG * HSZ / 4] = s1[i];
        }
        wd_s[tid] = Wd[tid];
    }
    __syncthreads();

    const float2* wc2 = reinterpret_cast<const float2*>(whc + wg * KCG * HSZ) + lp2;
    const float2* wg2 = reinterpret_cast<const float2*>(Wh)
                        + ((size_t)(rank * KH + wg * 128 + KCG)) * (HSZ / 2) + lp2;
    const float*  hgb = hsm + wg * 128 * KSTRIDE;   // this group's h rows
    const float2* xw2 = reinterpret_cast<const float2*>(g_xw);
    const uint32_t xb_base = smem_u32(xbf);

    for (int t = 0; t < TSZ; t++) {
        const int p = t & 1;

        float2 xr[CROWS];
        if (own) {
            #pragma unroll
            for (int r = 0; r < CROWS; r++)
                xr[r] = xw2[((size_t)t * BSZ + b0 + r) * (HSZ / 2) + lp2];
        }

        u64 A01 = 0, A23 = 0, A45 = 0, A67 = 0;
        u64 C01 = 0, C23 = 0, C45 = 0, C67 = 0;

        if (t > 0) {
            // ---- cached rows of this k-group ----
            #pragma unroll 8
            for (int k = 0; k < KCG; k++) {
                float2 w = wc2[k * (HSZ / 2)];
                ulonglong2 hA = *reinterpret_cast<const ulonglong2*>(hgb + k * KSTRIDE);
                ulonglong2 hB = *reinterpret_cast<const ulonglong2*>(hgb + k * KSTRIDE + 4);
                u64 wA = pack2(w.x, w.x), wB = pack2(w.y, w.y);
                ffma2(A01, wA, hA.x); ffma2(A23, wA, hA.y);
                ffma2(A45, wA, hB.x); ffma2(A67, wA, hB.y);
                ffma2(C01, wB, hA.x); ffma2(C23, wB, hA.y);
                ffma2(C45, wB, hB.x); ffma2(C67, wB, hB.y);
            }
            // ---- streamed rows with register prefetch ----
            float2 wreg[UPF];
            #pragma unroll
            for (int u = 0; u < UPF; u++)
                wreg[u] = wg2[u * (HSZ / 2)];

            for (int kb = KCG; kb < 128; kb += UPF) {
                float2 wcur[UPF];
                #pragma unroll
                for (int u = 0; u < UPF; u++) wcur[u] = wreg[u];
                if (kb + UPF < 128) {
                    #pragma unroll
                    for (int u = 0; u < UPF; u++)
                        wreg[u] = wg2[(size_t)(kb - KCG + UPF + u) * (HSZ / 2)];
                }
                #pragma unroll
                for (int u = 0; u < UPF; u++) {
                    int k = kb + u;
                    ulonglong2 hA = *reinterpret_cast<const ulonglong2*>(hgb + k * KSTRIDE);
                    ulonglong2 hB = *reinterpret_cast<const ulonglong2*>(hgb + k * KSTRIDE + 4);
                    u64 wA = pack2(wcur[u].x, wcur[u].x), wB = pack2(wcur[u].y, wcur[u].y);
                    ffma2(A01, wA, hA.x); ffma2(A23, wA, hA.y);
                    ffma2(A45, wA, hB.x); ffma2(A67, wA, hB.y);
                    ffma2(C01, wB, hA.x); ffma2(C23, wB, hA.y);
                    ffma2(C45, wB, hB.x); ffma2(C67, wB, hB.y);
                }
            }
        }

        float a0, a1, a2, a3, a4, a5, a6, a7;
        float c0, c1, c2, c3, c4, c5, c6, c7;
        unpack2(a0, a1, A01); unpack2(a2, a3, A23);
        unpack2(a4, a5, A45); unpack2(a6, a7, A67);
        unpack2(c0, c1, C01); unpack2(c2, c3, C23);
        unpack2(c4, c5, C45); unpack2(c6, c7, C67);

        // ---- wg1 -> wg0 reduction via conflict-free float4 scratch ----
        if (!g0) {
            red[0 * 256 + lp2] = make_float4(a0, a1, a2, a3);
            red[1 * 256 + lp2] = make_float4(a4, a5, a6, a7);
            red[2 * 256 + lp2] = make_float4(c0, c1, c2, c3);
            red[3 * 256 + lp2] = make_float4(c4, c5, c6, c7);
        }
        __syncthreads();   // S1: red visible; also all hsm reads drained

        if (g0) {
            float4 r0 = red[0 * 256 + lp2];
            float4 r1 = red[1 * 256 + lp2];
            float4 r2 = red[2 * 256 + lp2];
            float4 r3 = red[3 * 256 + lp2];
            a0 += r0.x; a1 += r0.y; a2 += r0.z; a3 += r0.w;
            a4 += r1.x; a5 += r1.y; a6 += r1.z; a7 += r1.w;
            c0 += r2.x; c1 += r2.y; c2 += r2.z; c3 += r2.w;
            c4 += r3.x; c5 += r3.y; c6 += r3.z; c7 += r3.w;

            if (!own) {
                float4* dst = reinterpret_cast<float4*>(xbf) + (p * 128 + lp) * 4;
                dst[0] = make_float4(a0, a1, a2, a3);
                dst[1] = make_float4(a4, a5, a6, a7);
                dst[2] = make_float4(c0, c1, c2, c3);
                dst[3] = make_float4(c4, c5, c6, c7);
            }
        }

        CLUSTER_SYNC();   // peer's foreign partials visible

        if (own) {
            uint32_t pa = mapa_peer(xb_base + (uint32_t)(p * 128 + lp) * 64, peer);
            float4 q0 = ld_cluster_f4(pa);
            float4 q1 = ld_cluster_f4(pa + 16);
            float4 q2 = ld_cluster_f4(pa + 32);
            float4 q3 = ld_cluster_f4(pa + 48);

            const int jlA = 2 * lp, jlB = jlA + 1;
            float* hA = hsm + jlA * KSTRIDE;
            float* hB = hsm + jlB * KSTRIDE;
            *reinterpret_cast<float4*>(hA) = make_float4(
                fmaxf(a0 + q0.x + xr[0].x, 0.f), fmaxf(a1 + q0.y + xr[1].x, 0.f),
                fmaxf(a2 + q0.z + xr[2].x, 0.f), fmaxf(a3 + q0.w + xr[3].x, 0.f));
            *reinterpret_cast<float4*>(hA + 4) = make_float4(
                fmaxf(a4 + q1.x + xr[4].x, 0.f), fmaxf(a5 + q1.y + xr[5].x, 0.f),
                fmaxf(a6 + q1.z + xr[6].x, 0.f), fmaxf(a7 + q1.w + xr[7].x, 0.f));
            *reinterpret_cast<float4*>(hB) = make_float4(
                fmaxf(c0 + q2.x + xr[0].y, 0.f), fmaxf(c1 + q2.y + xr[1].y, 0.f),
                fmaxf(c2 + q2.z + xr[2].y, 0.f), fmaxf(c3 + q2.w + xr[3].y, 0.f));
            *reinterpret_cast<float4*>(hB + 4) = make_float4(
                fmaxf(c4 + q3.x + xr[4].y, 0.f), fmaxf(c5 + q3.y + xr[5].y, 0.f),
                fmaxf(c6 + q3.z + xr[6].y, 0.f), fmaxf(c7 + q3.w + xr[7].y, 0.f));
        }
        __syncthreads();   // S2: h_t visible CTA-wide
    }

    // ---- final dense: out[b] = relu(h_T[b,:] @ W_d + b_d) ----
    {
        float s = 0.f;
        if (tid < 256) {
            const int wr = tid >> 5;      // warp 0..7 -> batch row
            const int l  = tid & 31;
            #pragma unroll
            for (int i = 0; i < 8; i++) {
                int jl = l * 8 + i;
                s += hsm[jl * KSTRIDE + wr] * wd_s[rank * KH + jl];
            }
            #pragma unroll
            for (int off = 16; off > 0; off >>= 1)
                s += __shfl_xor_sync(0xffffffffu, s, off);
            if (rank == 1 && l == 0) xbf[wr] = s;
        }
        CLUSTER_SYNC();
        if (rank == 0 && tid < 256 && (tid & 31) == 0) {
            int wr = tid >> 5;
            float sp = ld_cluster_f32(mapa_peer(xb_base + (uint32_t)wr * 4, peer));
            out[b0 + wr] = fmaxf(s + sp + bd[0], 0.f);
        }
        CLUSTER_SYNC();   // keep peer smem alive until reads complete
    }
}

extern "C" void kernel_launch(void* const* d_in, const int* in_sizes, int n_in,
                              void* d_out, int out_size) {
    const float* x    = (const float*)d_in[0];
    const float* Wx   = (const float*)d_in[1];
    const float* Wh   = (const float*)d_in[2];
    const float* brnn = (const float*)d_in[3];
    const float* Wd   = (const float*)d_in[4];
    const float* bd   = (const float*)d_in[5];
    float* out = (float*)d_out;

    cudaFuncSetAttribute(xw_kernel,
                         cudaFuncAttributeMaxDynamicSharedMemorySize, SMEM_XW_BYTES);
    cudaFuncSetAttribute(rnn_cluster_kernel,
                         cudaFuncAttributeMaxDynamicSharedMemorySize, SMEM_MAIN_BYTES);

    dim3 gxw(TSZ / TT, BSZ / 4);
    xw_kernel<<<gxw, NTHRX, SMEM_XW_BYTES>>>(x, Wx, brnn);
    rnn_cluster_kernel<<<NCTA, NTHR, SMEM_MAIN_BYTES>>>(Wh, Wd, bd, out);
}